// round 12
// baseline (speedup 1.0000x reference)
#include <cuda_runtime.h>
#include <cuda_fp16.h>
#include <cstdint>

#define TOK   4096
#define HID   2048
#define INTER 5632

// ---- scratch (device globals; no runtime allocation allowed) ----
__device__ __half g_xh[(size_t)TOK * HID];
__device__ __half g_wg[(size_t)INTER * HID];
__device__ __half g_wu[(size_t)INTER * HID];
__device__ __half g_wd[(size_t)HID * INTER];
__device__ __half g_hbuf[(size_t)TOK * INTER];

#define N4X ((TOK * HID) / 4)
#define N4W ((INTER * HID) / 4)
#define N4TOT (N4X + 3 * N4W)

__global__ __launch_bounds__(256)
void convert_all(const float* __restrict__ x,  const float* __restrict__ wg,
                 const float* __restrict__ wu, const float* __restrict__ wd,
                 __half* __restrict__ oxh, __half* __restrict__ owg,
                 __half* __restrict__ owu, __half* __restrict__ owd) {
  int i = blockIdx.x * blockDim.x + threadIdx.x;
  if (i >= N4TOT) return;
  const float* src;
  __half* dst;
  int off;
  if (i < N4X) { src = x; dst = oxh; off = i; }
  else {
    int j = i - N4X;
    int w = j / N4W;
    off = j - w * N4W;
    src = (w == 0) ? wg : (w == 1) ? wu : wd;
    dst = (w == 0) ? owg : (w == 1) ? owu : owd;
  }
  float4 v = reinterpret_cast<const float4*>(src)[off];
  __half2 h0 = __floats2half2_rn(v.x, v.y);
  __half2 h1 = __floats2half2_rn(v.z, v.w);
  reinterpret_cast<__half2*>(dst)[2 * off]     = h0;
  reinterpret_cast<__half2*>(dst)[2 * off + 1] = h1;
}

// =====================================================================
// helpers
// =====================================================================
__device__ __forceinline__ uint32_t smem_u32(const void* p) {
  uint32_t a;
  asm("{ .reg .u64 t; cvta.to.shared.u64 t, %1; cvt.u32.u64 %0, t; }" : "=r"(a) : "l"(p));
  return a;
}

__device__ __forceinline__ void mma16816(float* c, const uint32_t* a, const uint32_t* b) {
  asm volatile(
      "mma.sync.aligned.m16n8k16.row.col.f32.f16.f16.f32 "
      "{%0,%1,%2,%3}, {%4,%5,%6,%7}, {%8,%9}, {%0,%1,%2,%3};\n"
      : "+f"(c[0]), "+f"(c[1]), "+f"(c[2]), "+f"(c[3])
      : "r"(a[0]), "r"(a[1]), "r"(a[2]), "r"(a[3]), "r"(b[0]), "r"(b[1]));
}

__device__ __forceinline__ void ldsm4(uint32_t* r, uint32_t addr) {
  asm volatile("ldmatrix.sync.aligned.m8n8.x4.shared.b16 {%0,%1,%2,%3}, [%4];"
               : "=r"(r[0]), "=r"(r[1]), "=r"(r[2]), "=r"(r[3]) : "r"(addr));
}

__device__ __forceinline__ void cp16(uint32_t s, const void* g) {
  asm volatile("cp.async.cg.shared.global [%0], [%1], 16;" :: "r"(s), "l"(g));
}
#define CP_COMMIT() asm volatile("cp.async.commit_group;" ::: "memory")

// BK = 64 halves = 128 B/row; swizzled: row*128 + ((c ^ (row&7)) << 4)

// =====================================================================
// GEMM1 fused gate+up. CTA 128x64(x2), BK=64, 2-stage smem + 2-deep
// register fragment pipeline inside each kt.
// =====================================================================
__global__ __launch_bounds__(256, 2)
void gemm1_mma(const __half* __restrict__ X, const __half* __restrict__ Wg,
               const __half* __restrict__ Wu, const float* __restrict__ gs,
               const float* __restrict__ us, __half* __restrict__ Hout) {
  extern __shared__ char smem[];
  const uint32_t sb = smem_u32(smem);
  const int tid = threadIdx.x, lane = tid & 31, warp = tid >> 5;
  const int wm = warp & 3, wn = warp >> 2;
  const int mBase = blockIdx.y * 128;
  const int nBase = blockIdx.x * 64;
  const int s7 = lane & 7;

  const uint32_t aRow = (uint32_t)((wm * 32 + (lane & 15)) * 128);
  const int hiA = lane >> 4;
  const uint32_t bRow = (uint32_t)((wn * 32 + (lane & 7) + ((lane >> 4) & 1) * 8) * 128);
  const int cB = (lane >> 3) & 1;

  float ag[2][4][4], au[2][4][4];
#pragma unroll
  for (int i = 0; i < 2; i++)
#pragma unroll
    for (int j = 0; j < 4; j++)
#pragma unroll
      for (int k = 0; k < 4; k++) { ag[i][j][k] = 0.f; au[i][j][k] = 0.f; }

  auto load_stage = [&](int kt, int b) {
    const uint32_t base = sb + (uint32_t)b * 32768u;
    const int k0 = kt * 64;
#pragma unroll
    for (int i = 0; i < 4; i++) {
      int ch = tid + i * 256;
      int row = ch >> 3, c = ch & 7;
      uint32_t sw = (uint32_t)(row * 128 + ((c ^ (row & 7)) << 4));
      cp16(base + sw, X + (size_t)(mBase + row) * HID + k0 + c * 8);
    }
#pragma unroll
    for (int i = 0; i < 2; i++) {
      int ch = tid + i * 256;
      int row = ch >> 3, c = ch & 7;
      uint32_t sw = (uint32_t)(row * 128 + ((c ^ (row & 7)) << 4));
      cp16(base + 16384u + sw, Wg + (size_t)(nBase + row) * HID + k0 + c * 8);
      cp16(base + 24576u + sw, Wu + (size_t)(nBase + row) * HID + k0 + c * 8);
    }
    CP_COMMIT();
  };

  const int KT = HID / 64;  // 32
  load_stage(0, 0);
  load_stage(1, 1);

  // register fragment double buffers
  uint32_t a[2][2][4], bg[2][2][4], bu[2][2][4];

  for (int kt = 0; kt < KT; kt++) {
    const int b = kt & 1;
    if (kt + 1 < KT) asm volatile("cp.async.wait_group 1;" ::: "memory");
    else             asm volatile("cp.async.wait_group 0;" ::: "memory");
    __syncthreads();

    const uint32_t base = sb + (uint32_t)b * 32768u;
    const uint32_t aB = base + aRow;
    const uint32_t gB = base + 16384u + bRow;
    const uint32_t uB = base + 24576u + bRow;

    // prefetch kk=0 fragments
    {
      const uint32_t aOff = (uint32_t)(((hiA ^ s7)) << 4);
      ldsm4(a[0][0], aB + aOff);
      ldsm4(a[0][1], aB + 2048u + aOff);
      const uint32_t bOff = (uint32_t)(((cB ^ s7)) << 4);
      ldsm4(bg[0][0], gB + bOff);
      ldsm4(bg[0][1], gB + 2048u + bOff);
      ldsm4(bu[0][0], uB + bOff);
      ldsm4(bu[0][1], uB + 2048u + bOff);
    }
#pragma unroll
    for (int kk = 0; kk < 4; kk++) {
      const int cur = kk & 1, nxt = cur ^ 1;
      if (kk < 3) {  // prefetch kk+1 into the other buffer
        const uint32_t aOff = (uint32_t)(((((kk + 1) * 2 + hiA) ^ s7)) << 4);
        ldsm4(a[nxt][0], aB + aOff);
        ldsm4(a[nxt][1], aB + 2048u + aOff);
        const uint32_t bOff = (uint32_t)(((((kk + 1) * 2 + cB) ^ s7)) << 4);
        ldsm4(bg[nxt][0], gB + bOff);
        ldsm4(bg[nxt][1], gB + 2048u + bOff);
        ldsm4(bu[nxt][0], uB + bOff);
        ldsm4(bu[nxt][1], uB + 2048u + bOff);
      }
#pragma unroll
      for (int mt = 0; mt < 2; mt++)
#pragma unroll
        for (int np = 0; np < 2; np++) {
          mma16816(ag[mt][np * 2 + 0], a[cur][mt], &bg[cur][np][0]);
          mma16816(ag[mt][np * 2 + 1], a[cur][mt], &bg[cur][np][2]);
          mma16816(au[mt][np * 2 + 0], a[cur][mt], &bu[cur][np][0]);
          mma16816(au[mt][np * 2 + 1], a[cur][mt], &bu[cur][np][2]);
        }
    }
    __syncthreads();
    if (kt + 2 < KT) load_stage(kt + 2, b);
  }

  const int g = lane >> 2, t = lane & 3;
#pragma unroll
  for (int mt = 0; mt < 2; mt++) {
#pragma unroll
    for (int n8 = 0; n8 < 4; n8++) {
      const int col = nBase + wn * 32 + (n8 >> 1) * 16 + (n8 & 1) * 8 + 2 * t;
      const float gs0 = __ldg(gs + col), gs1 = __ldg(gs + col + 1);
      const float us0 = __ldg(us + col), us1 = __ldg(us + col + 1);
      const float* cg = ag[mt][n8];
      const float* cu = au[mt][n8];
      const int r = mBase + wm * 32 + mt * 16 + g;

      float g00 = cg[0] * gs0, g01 = cg[1] * gs1;
      float g10 = cg[2] * gs0, g11 = cg[3] * gs1;
      float u00 = cu[0] * us0, u01 = cu[1] * us1;
      float u10 = cu[2] * us0, u11 = cu[3] * us1;

      float h00 = g00 / (1.f + expf(-g00)) * u00;
      float h01 = g01 / (1.f + expf(-g01)) * u01;
      float h10 = g10 / (1.f + expf(-g10)) * u10;
      float h11 = g11 / (1.f + expf(-g11)) * u11;

      *reinterpret_cast<__half2*>(Hout + (size_t)r * INTER + col) =
          __floats2half2_rn(h00, h01);
      *reinterpret_cast<__half2*>(Hout + (size_t)(r + 8) * INTER + col) =
          __floats2half2_rn(h10, h11);
    }
  }
}

// =====================================================================
// GEMM2: out = (H @ Wd^T) * ds. CTA 128x128, BK=64, 2-stage smem +
// 2-deep register fragment pipeline.
// =====================================================================
__global__ __launch_bounds__(256, 2)
void gemm2_mma(const __half* __restrict__ H, const __half* __restrict__ Wd,
               const float* __restrict__ ds, float* __restrict__ Out) {
  extern __shared__ char smem[];
  const uint32_t sb = smem_u32(smem);
  const int tid = threadIdx.x, lane = tid & 31, warp = tid >> 5;
  const int wm = warp & 3, wn = warp >> 2;
  const int mBase = blockIdx.y * 128;
  const int nBase = blockIdx.x * 128;
  const int s7 = lane & 7;

  const uint32_t aRow = (uint32_t)((wm * 32 + (lane & 15)) * 128);
  const int hiA = lane >> 4;
  const uint32_t bRow = (uint32_t)((wn * 64 + (lane & 7) + ((lane >> 4) & 1) * 8) * 128);
  const int cB = (lane >> 3) & 1;

  float acc[2][8][4];
#pragma unroll
  for (int i = 0; i < 2; i++)
#pragma unroll
    for (int j = 0; j < 8; j++)
#pragma unroll
      for (int k = 0; k < 4; k++) acc[i][j][k] = 0.f;

  auto load_stage = [&](int kt, int b) {
    const uint32_t base = sb + (uint32_t)b * 32768u;
    const int k0 = kt * 64;
#pragma unroll
    for (int i = 0; i < 4; i++) {
      int ch = tid + i * 256;
      int row = ch >> 3, c = ch & 7;
      uint32_t sw = (uint32_t)(row * 128 + ((c ^ (row & 7)) << 4));
      cp16(base + sw,          H  + (size_t)(mBase + row) * INTER + k0 + c * 8);
      cp16(base + 16384u + sw, Wd + (size_t)(nBase + row) * INTER + k0 + c * 8);
    }
    CP_COMMIT();
  };

  const int KT = INTER / 64;  // 88
  load_stage(0, 0);
  load_stage(1, 1);

  uint32_t a[2][2][4], bf[2][4][4];

  for (int kt = 0; kt < KT; kt++) {
    const int b = kt & 1;
    if (kt + 1 < KT) asm volatile("cp.async.wait_group 1;" ::: "memory");
    else             asm volatile("cp.async.wait_group 0;" ::: "memory");
    __syncthreads();

    const uint32_t base = sb + (uint32_t)b * 32768u;
    const uint32_t aB = base + aRow;
    const uint32_t bB = base + 16384u + bRow;

    {
      const uint32_t aOff = (uint32_t)(((hiA ^ s7)) << 4);
      ldsm4(a[0][0], aB + aOff);
      ldsm4(a[0][1], aB + 2048u + aOff);
      const uint32_t bOff = (uint32_t)(((cB ^ s7)) << 4);
#pragma unroll
      for (int np = 0; np < 4; np++)
        ldsm4(bf[0][np], bB + (uint32_t)(np * 2048) + bOff);
    }
#pragma unroll
    for (int kk = 0; kk < 4; kk++) {
      const int cur = kk & 1, nxt = cur ^ 1;
      if (kk < 3) {
        const uint32_t aOff = (uint32_t)(((((kk + 1) * 2 + hiA) ^ s7)) << 4);
        ldsm4(a[nxt][0], aB + aOff);
        ldsm4(a[nxt][1], aB + 2048u + aOff);
        const uint32_t bOff = (uint32_t)(((((kk + 1) * 2 + cB) ^ s7)) << 4);
#pragma unroll
        for (int np = 0; np < 4; np++)
          ldsm4(bf[nxt][np], bB + (uint32_t)(np * 2048) + bOff);
      }
#pragma unroll
      for (int mt = 0; mt < 2; mt++)
#pragma unroll
        for (int np = 0; np < 4; np++) {
          mma16816(acc[mt][np * 2 + 0], a[cur][mt], &bf[cur][np][0]);
          mma16816(acc[mt][np * 2 + 1], a[cur][mt], &bf[cur][np][2]);
        }
    }
    __syncthreads();
    if (kt + 2 < KT) load_stage(kt + 2, b);
  }

  const int g = lane >> 2, t = lane & 3;
#pragma unroll
  for (int mt = 0; mt < 2; mt++) {
#pragma unroll
    for (int n8 = 0; n8 < 8; n8++) {
      const int col = nBase + wn * 64 + (n8 >> 1) * 16 + (n8 & 1) * 8 + 2 * t;
      const float d0 = __ldg(ds + col), d1 = __ldg(ds + col + 1);
      const float* cc = acc[mt][n8];
      const int r = mBase + wm * 32 + mt * 16 + g;
      *reinterpret_cast<float2*>(Out + (size_t)r * HID + col) =
          make_float2(cc[0] * d0, cc[1] * d1);
      *reinterpret_cast<float2*>(Out + (size_t)(r + 8) * HID + col) =
          make_float2(cc[2] * d0, cc[3] * d1);
    }
  }
}

// =====================================================================
extern "C" void kernel_launch(void* const* d_in, const int* in_sizes, int n_in,
                              void* d_out, int out_size) {
  const float* x      = (const float*)d_in[0];
  const float* gate_w = (const float*)d_in[1];
  const float* up_w   = (const float*)d_in[2];
  const float* down_w = (const float*)d_in[3];
  const float* gate_s = (const float*)d_in[4];
  const float* up_s   = (const float*)d_in[5];
  const float* down_s = (const float*)d_in[6];
  float* out = (float*)d_out;

  __half *xh, *wg, *wu, *wd, *hb;
  cudaGetSymbolAddress((void**)&xh, g_xh);
  cudaGetSymbolAddress((void**)&wg, g_wg);
  cudaGetSymbolAddress((void**)&wu, g_wu);
  cudaGetSymbolAddress((void**)&wd, g_wd);
  cudaGetSymbolAddress((void**)&hb, g_hbuf);

  const int SMEM = 65536;
  cudaFuncSetAttribute(gemm1_mma, cudaFuncAttributeMaxDynamicSharedMemorySize, SMEM);
  cudaFuncSetAttribute(gemm2_mma, cudaFuncAttributeMaxDynamicSharedMemorySize, SMEM);

  convert_all<<<(N4TOT + 255) / 256, 256>>>(x, gate_w, up_w, down_w, xh, wg, wu, wd);

  dim3 grid1(INTER / 64, TOK / 128);   // (88, 32)
  gemm1_mma<<<grid1, 256, SMEM>>>(xh, wg, wu, gate_s, up_s, hb);

  dim3 grid2(HID / 128, TOK / 128);    // (16, 32)
  gemm2_mma<<<grid2, 256, SMEM>>>(hb, wd, down_s, out);
}

// round 14
// speedup vs baseline: 1.0468x; 1.0468x over previous
#include <cuda_runtime.h>
#include <cuda_fp16.h>
#include <cstdint>

#define TOK   4096
#define HID   2048
#define INTER 5632

// ---- scratch (device globals; no runtime allocation allowed) ----
__device__ __half g_xh[(size_t)TOK * HID];
__device__ __half g_wg[(size_t)INTER * HID];
__device__ __half g_wu[(size_t)INTER * HID];
__device__ __half g_wd[(size_t)HID * INTER];
__device__ __half g_hbuf[(size_t)TOK * INTER];

#define N4X ((TOK * HID) / 4)          // 2,097,152 float4
#define N4W ((INTER * HID) / 4)        // 2,883,584 float4
#define N4TOT3 (N4X + 2 * N4W)         // x + wg + wu = 7,864,320 (= 30720*256)

// ---- fused fp32 -> fp16 conversion for x, gate_w, up_w ----
__global__ __launch_bounds__(256)
void convert_xgu(const float* __restrict__ x,  const float* __restrict__ wg,
                 const float* __restrict__ wu,
                 __half* __restrict__ oxh, __half* __restrict__ owg,
                 __half* __restrict__ owu) {
  int i = blockIdx.x * blockDim.x + threadIdx.x;
  if (i >= N4TOT3) return;
  const float* src;
  __half* dst;
  int off;
  if (i < N4X) { src = x; dst = oxh; off = i; }
  else {
    int j = i - N4X;
    if (j < N4W) { src = wg; dst = owg; off = j; }
    else         { src = wu; dst = owu; off = j - N4W; }
  }
  float4 v = reinterpret_cast<const float4*>(src)[off];
  __half2 h0 = __floats2half2_rn(v.x, v.y);
  __half2 h1 = __floats2half2_rn(v.z, v.w);
  reinterpret_cast<__half2*>(dst)[2 * off]     = h0;
  reinterpret_cast<__half2*>(dst)[2 * off + 1] = h1;
}

// =====================================================================
// helpers
// =====================================================================
__device__ __forceinline__ uint32_t smem_u32(const void* p) {
  uint32_t a;
  asm("{ .reg .u64 t; cvta.to.shared.u64 t, %1; cvt.u32.u64 %0, t; }" : "=r"(a) : "l"(p));
  return a;
}

__device__ __forceinline__ void mma16816(float* c, const uint32_t* a, const uint32_t* b) {
  asm volatile(
      "mma.sync.aligned.m16n8k16.row.col.f32.f16.f16.f32 "
      "{%0,%1,%2,%3}, {%4,%5,%6,%7}, {%8,%9}, {%0,%1,%2,%3};\n"
      : "+f"(c[0]), "+f"(c[1]), "+f"(c[2]), "+f"(c[3])
      : "r"(a[0]), "r"(a[1]), "r"(a[2]), "r"(a[3]), "r"(b[0]), "r"(b[1]));
}

__device__ __forceinline__ void ldsm4(uint32_t* r, uint32_t addr) {
  asm volatile("ldmatrix.sync.aligned.m8n8.x4.shared.b16 {%0,%1,%2,%3}, [%4];"
               : "=r"(r[0]), "=r"(r[1]), "=r"(r[2]), "=r"(r[3]) : "r"(addr));
}

__device__ __forceinline__ void cp16(uint32_t s, const void* g) {
  asm volatile("cp.async.cg.shared.global [%0], [%1], 16;" :: "r"(s), "l"(g));
}
#define CP_COMMIT() asm volatile("cp.async.commit_group;" ::: "memory")

// BK = 64 halves = 128 bytes per row -> canonical SW128 swizzle.
// smem byte offset of (row, 16B-chunk c):  row*128 + ((c ^ (row&7)) << 4)

// =====================================================================
// GEMM1 fused gate+up (R9 champion) + hidden down_w fp32->fp16 convert
// in the prologue (overlaps stage-0/1 cp.async DRAM latency).
// =====================================================================
__global__ __launch_bounds__(256, 2)
void gemm1_mma(const __half* __restrict__ X, const __half* __restrict__ Wg,
               const __half* __restrict__ Wu, const float* __restrict__ gs,
               const float* __restrict__ us, __half* __restrict__ Hout,
               const float* __restrict__ wd_f32, __half* __restrict__ wd_f16) {
  extern __shared__ char smem[];
  const uint32_t sb = smem_u32(smem);
  const int tid = threadIdx.x, lane = tid & 31, warp = tid >> 5;
  const int wm = warp & 3, wn = warp >> 2;       // wn in {0,1}
  const int mBase = blockIdx.y * 128;
  const int nBase = blockIdx.x * 64;
  const int s7 = lane & 7;

  const uint32_t aRow = (uint32_t)((wm * 32 + (lane & 15)) * 128);
  const int hiA = lane >> 4;
  const uint32_t bRow = (uint32_t)((wn * 32 + (lane & 7) + ((lane >> 4) & 1) * 8) * 128);
  const int cB = (lane >> 3) & 1;

  float ag[2][4][4], au[2][4][4];
#pragma unroll
  for (int i = 0; i < 2; i++)
#pragma unroll
    for (int j = 0; j < 4; j++)
#pragma unroll
      for (int k = 0; k < 4; k++) { ag[i][j][k] = 0.f; au[i][j][k] = 0.f; }

  auto load_stage = [&](int kt, int b) {
    const uint32_t base = sb + (uint32_t)b * 32768u;
    const int k0 = kt * 64;
#pragma unroll
    for (int i = 0; i < 4; i++) {               // A: 1024 chunks / 256 thr
      int ch = tid + i * 256;
      int row = ch >> 3, c = ch & 7;
      uint32_t sw = (uint32_t)(row * 128 + ((c ^ (row & 7)) << 4));
      cp16(base + sw, X + (size_t)(mBase + row) * HID + k0 + c * 8);
    }
#pragma unroll
    for (int i = 0; i < 2; i++) {               // Bg,Bu: 512 chunks each
      int ch = tid + i * 256;
      int row = ch >> 3, c = ch & 7;
      uint32_t sw = (uint32_t)(row * 128 + ((c ^ (row & 7)) << 4));
      cp16(base + 16384u + sw, Wg + (size_t)(nBase + row) * HID + k0 + c * 8);
      cp16(base + 24576u + sw, Wu + (size_t)(nBase + row) * HID + k0 + c * 8);
    }
    CP_COMMIT();
  };

  const int KT = HID / 64;  // 32
  load_stage(0, 0);
  load_stage(1, 1);

  // ---- hidden down_w conversion: this CTA's 1024-float4 slice ----
  {
    const int nCta = gridDim.x * gridDim.y;              // 2816
    const int bid = blockIdx.y * gridDim.x + blockIdx.x;
    // N4W = 2,883,584 = 2816 * 1024 exactly
    const int per = (int)(N4W / 2816);                   // 1024
    size_t s0 = (size_t)bid * per;
    if (bid < nCta) {
#pragma unroll
      for (int i = 0; i < 4; i++) {
        size_t idx = s0 + tid + i * 256;
        float4 v = reinterpret_cast<const float4*>(wd_f32)[idx];
        __half2 h0 = __floats2half2_rn(v.x, v.y);
        __half2 h1 = __floats2half2_rn(v.z, v.w);
        reinterpret_cast<__half2*>(wd_f16)[2 * idx]     = h0;
        reinterpret_cast<__half2*>(wd_f16)[2 * idx + 1] = h1;
      }
    }
  }

  for (int kt = 0; kt < KT; kt++) {
    const int b = kt & 1;
    if (kt + 1 < KT) asm volatile("cp.async.wait_group 1;" ::: "memory");
    else             asm volatile("cp.async.wait_group 0;" ::: "memory");
    __syncthreads();

    const uint32_t base = sb + (uint32_t)b * 32768u;
    const uint32_t aB = base + aRow;
    const uint32_t gB = base + 16384u + bRow;
    const uint32_t uB = base + 24576u + bRow;
#pragma unroll
    for (int kk = 0; kk < 4; kk++) {
      const uint32_t aOff = (uint32_t)((((kk * 2 + hiA) ^ s7)) << 4);
      uint32_t a[2][4];
      ldsm4(a[0], aB + aOff);
      ldsm4(a[1], aB + 2048u + aOff);
      const uint32_t bOff = (uint32_t)((((kk * 2 + cB) ^ s7)) << 4);
      uint32_t bg[2][4], bu[2][4];
#pragma unroll
      for (int np = 0; np < 2; np++) {
        ldsm4(bg[np], gB + (uint32_t)(np * 2048) + bOff);
        ldsm4(bu[np], uB + (uint32_t)(np * 2048) + bOff);
      }
#pragma unroll
      for (int mt = 0; mt < 2; mt++)
#pragma unroll
        for (int np = 0; np < 2; np++) {
          mma16816(ag[mt][np * 2 + 0], a[mt], &bg[np][0]);
          mma16816(ag[mt][np * 2 + 1], a[mt], &bg[np][2]);
          mma16816(au[mt][np * 2 + 0], a[mt], &bu[np][0]);
          mma16816(au[mt][np * 2 + 1], a[mt], &bu[np][2]);
        }
    }
    __syncthreads();
    if (kt + 2 < KT) load_stage(kt + 2, b);
  }

  // epilogue: dequant + silu-gate, fp16 out
  const int g = lane >> 2, t = lane & 3;
#pragma unroll
  for (int mt = 0; mt < 2; mt++) {
#pragma unroll
    for (int n8 = 0; n8 < 4; n8++) {
      const int col = nBase + wn * 32 + (n8 >> 1) * 16 + (n8 & 1) * 8 + 2 * t;
      const float gs0 = __ldg(gs + col), gs1 = __ldg(gs + col + 1);
      const float us0 = __ldg(us + col), us1 = __ldg(us + col + 1);
      const float* cg = ag[mt][n8];
      const float* cu = au[mt][n8];
      const int r = mBase + wm * 32 + mt * 16 + g;

      float g00 = cg[0] * gs0, g01 = cg[1] * gs1;
      float g10 = cg[2] * gs0, g11 = cg[3] * gs1;
      float u00 = cu[0] * us0, u01 = cu[1] * us1;
      float u10 = cu[2] * us0, u11 = cu[3] * us1;

      float h00 = g00 / (1.f + expf(-g00)) * u00;
      float h01 = g01 / (1.f + expf(-g01)) * u01;
      float h10 = g10 / (1.f + expf(-g10)) * u10;
      float h11 = g11 / (1.f + expf(-g11)) * u11;

      *reinterpret_cast<__half2*>(Hout + (size_t)r * INTER + col) =
          __floats2half2_rn(h00, h01);
      *reinterpret_cast<__half2*>(Hout + (size_t)(r + 8) * INTER + col) =
          __floats2half2_rn(h10, h11);
    }
  }
}

// =====================================================================
// GEMM2 (R9 champion): out = (H @ Wd^T) * ds, fp32 out. CTA 128x128.
// =====================================================================
__global__ __launch_bounds__(256, 2)
void gemm2_mma(const __half* __restrict__ H, const __half* __restrict__ Wd,
               const float* __restrict__ ds, float* __restrict__ Out) {
  extern __shared__ char smem[];
  const uint32_t sb = smem_u32(smem);
  const int tid = threadIdx.x, lane = tid & 31, warp = tid >> 5;
  const int wm = warp & 3, wn = warp >> 2;       // wn in {0,1}
  const int mBase = blockIdx.y * 128;
  const int nBase = blockIdx.x * 128;
  const int s7 = lane & 7;

  const uint32_t aRow = (uint32_t)((wm * 32 + (lane & 15)) * 128);
  const int hiA = lane >> 4;
  const uint32_t bRow = (uint32_t)((wn * 64 + (lane & 7) + ((lane >> 4) & 1) * 8) * 128);
  const int cB = (lane >> 3) & 1;

  float acc[2][8][4];
#pragma unroll
  for (int i = 0; i < 2; i++)
#pragma unroll
    for (int j = 0; j < 8; j++)
#pragma unroll
      for (int k = 0; k < 4; k++) acc[i][j][k] = 0.f;

  auto load_stage = [&](int kt, int b) {
    const uint32_t base = sb + (uint32_t)b * 32768u;
    const int k0 = kt * 64;
#pragma unroll
    for (int i = 0; i < 4; i++) {
      int ch = tid + i * 256;
      int row = ch >> 3, c = ch & 7;
      uint32_t sw = (uint32_t)(row * 128 + ((c ^ (row & 7)) << 4));
      cp16(base + sw,          H  + (size_t)(mBase + row) * INTER + k0 + c * 8);
      cp16(base + 16384u + sw, Wd + (size_t)(nBase + row) * INTER + k0 + c * 8);
    }
    CP_COMMIT();
  };

  const int KT = INTER / 64;  // 88
  load_stage(0, 0);
  load_stage(1, 1);

  for (int kt = 0; kt < KT; kt++) {
    const int b = kt & 1;
    if (kt + 1 < KT) asm volatile("cp.async.wait_group 1;" ::: "memory");
    else             asm volatile("cp.async.wait_group 0;" ::: "memory");
    __syncthreads();

    const uint32_t base = sb + (uint32_t)b * 32768u;
    const uint32_t aB = base + aRow;
    const uint32_t bB = base + 16384u + bRow;
#pragma unroll
    for (int kk = 0; kk < 4; kk++) {
      const uint32_t aOff = (uint32_t)((((kk * 2 + hiA) ^ s7)) << 4);
      uint32_t a[2][4];
      ldsm4(a[0], aB + aOff);
      ldsm4(a[1], aB + 2048u + aOff);
      const uint32_t bOff = (uint32_t)((((kk * 2 + cB) ^ s7)) << 4);
      uint32_t bf[4][4];
#pragma unroll
      for (int np = 0; np < 4; np++)
        ldsm4(bf[np], bB + (uint32_t)(np * 2048) + bOff);
#pragma unroll
      for (int mt = 0; mt < 2; mt++)
#pragma unroll
        for (int np = 0; np < 4; np++) {
          mma16816(acc[mt][np * 2 + 0], a[mt], &bf[np][0]);
          mma16816(acc[mt][np * 2 + 1], a[mt], &bf[np][2]);
        }
    }
    __syncthreads();
    if (kt + 2 < KT) load_stage(kt + 2, b);
  }

  const int g = lane >> 2, t = lane & 3;
#pragma unroll
  for (int mt = 0; mt < 2; mt++) {
#pragma unroll
    for (int n8 = 0; n8 < 8; n8++) {
      const int col = nBase + wn * 64 + (n8 >> 1) * 16 + (n8 & 1) * 8 + 2 * t;
      const float d0 = __ldg(ds + col), d1 = __ldg(ds + col + 1);
      const float* cc = acc[mt][n8];
      const int r = mBase + wm * 32 + mt * 16 + g;
      *reinterpret_cast<float2*>(Out + (size_t)r * HID + col) =
          make_float2(cc[0] * d0, cc[1] * d1);
      *reinterpret_cast<float2*>(Out + (size_t)(r + 8) * HID + col) =
          make_float2(cc[2] * d0, cc[3] * d1);
    }
  }
}

// =====================================================================
extern "C" void kernel_launch(void* const* d_in, const int* in_sizes, int n_in,
                              void* d_out, int out_size) {
  const float* x      = (const float*)d_in[0];
  const float* gate_w = (const float*)d_in[1];
  const float* up_w   = (const float*)d_in[2];
  const float* down_w = (const float*)d_in[3];
  const float* gate_s = (const float*)d_in[4];
  const float* up_s   = (const float*)d_in[5];
  const float* down_s = (const float*)d_in[6];
  float* out = (float*)d_out;

  __half *xh, *wg, *wu, *wd, *hb;
  cudaGetSymbolAddress((void**)&xh, g_xh);
  cudaGetSymbolAddress((void**)&wg, g_wg);
  cudaGetSymbolAddress((void**)&wu, g_wu);
  cudaGetSymbolAddress((void**)&wd, g_wd);
  cudaGetSymbolAddress((void**)&hb, g_hbuf);

  const int SMEM = 65536;  // 2 stages x 32KB, both GEMMs
  cudaFuncSetAttribute(gemm1_mma, cudaFuncAttributeMaxDynamicSharedMemorySize, SMEM);
  cudaFuncSetAttribute(gemm2_mma, cudaFuncAttributeMaxDynamicSharedMemorySize, SMEM);

  // convert x, gate_w, up_w only; down_w converts inside gemm1
  convert_xgu<<<(N4TOT3 + 255) / 256, 256>>>(x, gate_w, up_w, xh, wg, wu);

  dim3 grid1(INTER / 64, TOK / 128);   // (88, 32) = 2816 CTAs
  gemm1_mma<<<grid1, 256, SMEM>>>(xh, wg, wu, gate_s, up_s, hb, down_w, wd);

  dim3 grid2(HID / 128, TOK / 128);    // (16, 32)
  gemm2_mma<<<grid2, 256, SMEM>>>(hb, wd, down_s, out);
}

// round 15
// speedup vs baseline: 1.0472x; 1.0004x over previous
#include <cuda_runtime.h>
#include <cuda_fp16.h>
#include <cstdint>

#define TOK   4096
#define HID   2048
#define INTER 5632

// ---- scratch (device globals; no runtime allocation allowed) ----
__device__ __half g_xh[(size_t)TOK * HID];
__device__ __half g_wg[(size_t)INTER * HID];
__device__ __half g_wu[(size_t)INTER * HID];
__device__ __half g_wd[(size_t)HID * INTER];
__device__ __half g_hbuf[(size_t)TOK * INTER];

// ---- cross-phase sync state (zeroed by convert_xgu each call) ----
__device__ int g_q1;             // gemm1 work queue
__device__ int g_q2;             // gemm2 work queue
__device__ int g_wdd;            // wd-conversion done count (704 expected)
__device__ int g_rowdone[32];    // per-128-row-block gemm1 completion (88 expected)

#define G1_TASKS 2816            // 32 mb x 88 nb
#define G2_TASKS 512             // 32 mb x 16 nb
#define WD_TASKS 704             // first 704 gemm1 tasks convert wd
#define N4X ((TOK * HID) / 4)
#define N4W ((INTER * HID) / 4)  // 2,883,584 = 704 * 4096
#define N4TOT3 (N4X + 2 * N4W)

// ---- fused fp32 -> fp16 conversion for x, gate_w, up_w + counter reset ----
__global__ __launch_bounds__(256)
void convert_xgu(const float* __restrict__ x,  const float* __restrict__ wg,
                 const float* __restrict__ wu,
                 __half* __restrict__ oxh, __half* __restrict__ owg,
                 __half* __restrict__ owu) {
  int i = blockIdx.x * blockDim.x + threadIdx.x;
  if (i == 0) {
    g_q1 = 0; g_q2 = 0; g_wdd = 0;
#pragma unroll
    for (int r = 0; r < 32; r++) g_rowdone[r] = 0;
  }
  if (i >= N4TOT3) return;
  const float* src;
  __half* dst;
  int off;
  if (i < N4X) { src = x; dst = oxh; off = i; }
  else {
    int j = i - N4X;
    if (j < N4W) { src = wg; dst = owg; off = j; }
    else         { src = wu; dst = owu; off = j - N4W; }
  }
  float4 v = reinterpret_cast<const float4*>(src)[off];
  __half2 h0 = __floats2half2_rn(v.x, v.y);
  __half2 h1 = __floats2half2_rn(v.z, v.w);
  reinterpret_cast<__half2*>(dst)[2 * off]     = h0;
  reinterpret_cast<__half2*>(dst)[2 * off + 1] = h1;
}

// =====================================================================
// helpers
// =====================================================================
__device__ __forceinline__ uint32_t smem_u32(const void* p) {
  uint32_t a;
  asm("{ .reg .u64 t; cvta.to.shared.u64 t, %1; cvt.u32.u64 %0, t; }" : "=r"(a) : "l"(p));
  return a;
}
__device__ __forceinline__ void mma16816(float* c, const uint32_t* a, const uint32_t* b) {
  asm volatile(
      "mma.sync.aligned.m16n8k16.row.col.f32.f16.f16.f32 "
      "{%0,%1,%2,%3}, {%4,%5,%6,%7}, {%8,%9}, {%0,%1,%2,%3};\n"
      : "+f"(c[0]), "+f"(c[1]), "+f"(c[2]), "+f"(c[3])
      : "r"(a[0]), "r"(a[1]), "r"(a[2]), "r"(a[3]), "r"(b[0]), "r"(b[1]));
}
__device__ __forceinline__ void ldsm4(uint32_t* r, uint32_t addr) {
  asm volatile("ldmatrix.sync.aligned.m8n8.x4.shared.b16 {%0,%1,%2,%3}, [%4];"
               : "=r"(r[0]), "=r"(r[1]), "=r"(r[2]), "=r"(r[3]) : "r"(addr));
}
__device__ __forceinline__ void cp16(uint32_t s, const void* g) {
  asm volatile("cp.async.cg.shared.global [%0], [%1], 16;" :: "r"(s), "l"(g));
}
#define CP_COMMIT() asm volatile("cp.async.commit_group;" ::: "memory")
__device__ __forceinline__ int ldvol(const int* p) {
  int v;
  asm volatile("ld.volatile.global.s32 %0, [%1];" : "=r"(v) : "l"(p));
  return v;
}

#define SMEM_BYTES (65536 + 16)   // 2x32KB stages + broadcast slot

// =====================================================================
// Persistent fused kernel: phase 1 = gemm1 tiles (queue), phase 2 =
// gemm2 tiles (queue, gated on row readiness).
// =====================================================================
__global__ __launch_bounds__(256, 2)
void fused_mlp(const __half* __restrict__ X, const __half* __restrict__ Wg,
               const __half* __restrict__ Wu, const float* __restrict__ gs,
               const float* __restrict__ us, __half* __restrict__ Hout,
               const float* __restrict__ wd_f32, __half* __restrict__ wd_f16,
               const float* __restrict__ ds, float* __restrict__ Out) {
  extern __shared__ char smem[];
  const uint32_t sb = smem_u32(smem);
  volatile int* bcast = reinterpret_cast<volatile int*>(smem + 65536);
  const int tid = threadIdx.x, lane = tid & 31, warp = tid >> 5;
  const int wm = warp & 3, wn = warp >> 2;
  const int s7 = lane & 7;

  const uint32_t aRow = (uint32_t)((wm * 32 + (lane & 15)) * 128);
  const int hiA = lane >> 4;
  const uint32_t bRow1 = (uint32_t)((wn * 32 + (lane & 7) + ((lane >> 4) & 1) * 8) * 128);
  const uint32_t bRow2 = (uint32_t)((wn * 64 + (lane & 7) + ((lane >> 4) & 1) * 8) * 128);
  const int cB = (lane >> 3) & 1;
  const int g = lane >> 2, t4 = lane & 3;

  // ================= phase 1: gemm1 tiles =================
  for (;;) {
    if (tid == 0) *bcast = atomicAdd(&g_q1, 1);
    __syncthreads();
    const int task = *bcast;
    __syncthreads();
    if (task >= G1_TASKS) break;
    const int mb = task / 88, nb = task - mb * 88;
    const int mBase = mb * 128, nBase = nb * 64;
    const bool early = (task < WD_TASKS);

    float ag[2][4][4], au[2][4][4];
#pragma unroll
    for (int i = 0; i < 2; i++)
#pragma unroll
      for (int j = 0; j < 4; j++)
#pragma unroll
        for (int k = 0; k < 4; k++) { ag[i][j][k] = 0.f; au[i][j][k] = 0.f; }

    auto load_stage = [&](int kt, int b) {
      const uint32_t base = sb + (uint32_t)b * 32768u;
      const int k0 = kt * 64;
#pragma unroll
      for (int i = 0; i < 4; i++) {
        int ch = tid + i * 256;
        int row = ch >> 3, c = ch & 7;
        uint32_t sw = (uint32_t)(row * 128 + ((c ^ (row & 7)) << 4));
        cp16(base + sw, X + (size_t)(mBase + row) * HID + k0 + c * 8);
      }
#pragma unroll
      for (int i = 0; i < 2; i++) {
        int ch = tid + i * 256;
        int row = ch >> 3, c = ch & 7;
        uint32_t sw = (uint32_t)(row * 128 + ((c ^ (row & 7)) << 4));
        cp16(base + 16384u + sw, Wg + (size_t)(nBase + row) * HID + k0 + c * 8);
        cp16(base + 24576u + sw, Wu + (size_t)(nBase + row) * HID + k0 + c * 8);
      }
      CP_COMMIT();
    };

    const int KT = HID / 64;  // 32
    load_stage(0, 0);
    load_stage(1, 1);

    // hidden wd conversion: first 704 tasks convert 4096 float4 each
    if (early) {
      size_t s0 = (size_t)task * 4096;
#pragma unroll
      for (int i = 0; i < 16; i++) {
        size_t idx = s0 + tid + i * 256;
        float4 v = reinterpret_cast<const float4*>(wd_f32)[idx];
        __half2 h0 = __floats2half2_rn(v.x, v.y);
        __half2 h1 = __floats2half2_rn(v.z, v.w);
        reinterpret_cast<__half2*>(wd_f16)[2 * idx]     = h0;
        reinterpret_cast<__half2*>(wd_f16)[2 * idx + 1] = h1;
      }
    }

    for (int kt = 0; kt < KT; kt++) {
      const int b = kt & 1;
      if (kt + 1 < KT) asm volatile("cp.async.wait_group 1;" ::: "memory");
      else             asm volatile("cp.async.wait_group 0;" ::: "memory");
      __syncthreads();
      if (kt == 0 && early && tid == 0) {
        __threadfence();
        atomicAdd(&g_wdd, 1);
      }

      const uint32_t base = sb + (uint32_t)b * 32768u;
      const uint32_t aB = base + aRow;
      const uint32_t gB = base + 16384u + bRow1;
      const uint32_t uB = base + 24576u + bRow1;
#pragma unroll
      for (int kk = 0; kk < 4; kk++) {
        const uint32_t aOff = (uint32_t)((((kk * 2 + hiA) ^ s7)) << 4);
        uint32_t a[2][4];
        ldsm4(a[0], aB + aOff);
        ldsm4(a[1], aB + 2048u + aOff);
        const uint32_t bOff = (uint32_t)((((kk * 2 + cB) ^ s7)) << 4);
        uint32_t bg[2][4], bu[2][4];
#pragma unroll
        for (int np = 0; np < 2; np++) {
          ldsm4(bg[np], gB + (uint32_t)(np * 2048) + bOff);
          ldsm4(bu[np], uB + (uint32_t)(np * 2048) + bOff);
        }
#pragma unroll
        for (int mt = 0; mt < 2; mt++)
#pragma unroll
          for (int np = 0; np < 2; np++) {
            mma16816(ag[mt][np * 2 + 0], a[mt], &bg[np][0]);
            mma16816(ag[mt][np * 2 + 1], a[mt], &bg[np][2]);
            mma16816(au[mt][np * 2 + 0], a[mt], &bu[np][0]);
            mma16816(au[mt][np * 2 + 1], a[mt], &bu[np][2]);
          }
      }
      __syncthreads();
      if (kt + 2 < KT) load_stage(kt + 2, b);
    }

    // epilogue: dequant + silu-gate, fp16 out
#pragma unroll
    for (int mt = 0; mt < 2; mt++) {
#pragma unroll
      for (int n8 = 0; n8 < 4; n8++) {
        const int col = nBase + wn * 32 + (n8 >> 1) * 16 + (n8 & 1) * 8 + 2 * t4;
        const float gs0 = __ldg(gs + col), gs1 = __ldg(gs + col + 1);
        const float us0 = __ldg(us + col), us1 = __ldg(us + col + 1);
        const float* cg = ag[mt][n8];
        const float* cu = au[mt][n8];
        const int r = mBase + wm * 32 + mt * 16 + g;

        float g00 = cg[0] * gs0, g01 = cg[1] * gs1;
        float g10 = cg[2] * gs0, g11 = cg[3] * gs1;
        float u00 = cu[0] * us0, u01 = cu[1] * us1;
        float u10 = cu[2] * us0, u11 = cu[3] * us1;

        float h00 = g00 / (1.f + expf(-g00)) * u00;
        float h01 = g01 / (1.f + expf(-g01)) * u01;
        float h10 = g10 / (1.f + expf(-g10)) * u10;
        float h11 = g11 / (1.f + expf(-g11)) * u11;

        *reinterpret_cast<__half2*>(Hout + (size_t)r * INTER + col) =
            __floats2half2_rn(h00, h01);
        *reinterpret_cast<__half2*>(Hout + (size_t)(r + 8) * INTER + col) =
            __floats2half2_rn(h10, h11);
      }
    }
    __syncthreads();   // all H stores issued CTA-wide
    if (tid == 0) {
      __threadfence();
      atomicAdd(&g_rowdone[mb], 1);
    }
  }

  // ================= phase 2: gemm2 tiles =================
  for (;;) {
    if (tid == 0) *bcast = atomicAdd(&g_q2, 1);
    __syncthreads();
    const int task = *bcast;
    __syncthreads();
    if (task >= G2_TASKS) break;
    const int mb = task / 16, nb = task - mb * 16;
    const int mBase = mb * 128, nBase = nb * 128;

    // wait for wd conversion + this row block's H
    if (tid == 0) {
      while (ldvol(&g_wdd) < WD_TASKS) {}
      while (ldvol(&g_rowdone[mb]) < 88) {}
      __threadfence();
    }
    __syncthreads();

    float acc[2][8][4];
#pragma unroll
    for (int i = 0; i < 2; i++)
#pragma unroll
      for (int j = 0; j < 8; j++)
#pragma unroll
        for (int k = 0; k < 4; k++) acc[i][j][k] = 0.f;

    auto load_stage2 = [&](int kt, int b) {
      const uint32_t base = sb + (uint32_t)b * 32768u;
      const int k0 = kt * 64;
#pragma unroll
      for (int i = 0; i < 4; i++) {
        int ch = tid + i * 256;
        int row = ch >> 3, c = ch & 7;
        uint32_t sw = (uint32_t)(row * 128 + ((c ^ (row & 7)) << 4));
        cp16(base + sw,          Hout  + (size_t)(mBase + row) * INTER + k0 + c * 8);
        cp16(base + 16384u + sw, wd_f16 + (size_t)(nBase + row) * INTER + k0 + c * 8);
      }
      CP_COMMIT();
    };

    const int KT = INTER / 64;  // 88
    load_stage2(0, 0);
    load_stage2(1, 1);

    for (int kt = 0; kt < KT; kt++) {
      const int b = kt & 1;
      if (kt + 1 < KT) asm volatile("cp.async.wait_group 1;" ::: "memory");
      else             asm volatile("cp.async.wait_group 0;" ::: "memory");
      __syncthreads();

      const uint32_t base = sb + (uint32_t)b * 32768u;
      const uint32_t aB = base + aRow;
      const uint32_t bB = base + 16384u + bRow2;
#pragma unroll
      for (int kk = 0; kk < 4; kk++) {
        const uint32_t aOff = (uint32_t)((((kk * 2 + hiA) ^ s7)) << 4);
        uint32_t a[2][4];
        ldsm4(a[0], aB + aOff);
        ldsm4(a[1], aB + 2048u + aOff);
        const uint32_t bOff = (uint32_t)((((kk * 2 + cB) ^ s7)) << 4);
        uint32_t bf[4][4];
#pragma unroll
        for (int np = 0; np < 4; np++)
          ldsm4(bf[np], bB + (uint32_t)(np * 2048) + bOff);
#pragma unroll
        for (int mt = 0; mt < 2; mt++)
#pragma unroll
          for (int np = 0; np < 4; np++) {
            mma16816(acc[mt][np * 2 + 0], a[mt], &bf[np][0]);
            mma16816(acc[mt][np * 2 + 1], a[mt], &bf[np][2]);
          }
      }
      __syncthreads();
      if (kt + 2 < KT) load_stage2(kt + 2, b);
    }

#pragma unroll
    for (int mt = 0; mt < 2; mt++) {
#pragma unroll
      for (int n8 = 0; n8 < 8; n8++) {
        const int col = nBase + wn * 64 + (n8 >> 1) * 16 + (n8 & 1) * 8 + 2 * t4;
        const float d0 = __ldg(ds + col), d1 = __ldg(ds + col + 1);
        const float* cc = acc[mt][n8];
        const int r = mBase + wm * 32 + mt * 16 + g;
        *reinterpret_cast<float2*>(Out + (size_t)r * HID + col) =
            make_float2(cc[0] * d0, cc[1] * d1);
        *reinterpret_cast<float2*>(Out + (size_t)(r + 8) * HID + col) =
            make_float2(cc[2] * d0, cc[3] * d1);
      }
    }
  }
}

// =====================================================================
extern "C" void kernel_launch(void* const* d_in, const int* in_sizes, int n_in,
                              void* d_out, int out_size) {
  const float* x      = (const float*)d_in[0];
  const float* gate_w = (const float*)d_in[1];
  const float* up_w   = (const float*)d_in[2];
  const float* down_w = (const float*)d_in[3];
  const float* gate_s = (const float*)d_in[4];
  const float* up_s   = (const float*)d_in[5];
  const float* down_s = (const float*)d_in[6];
  float* out = (float*)d_out;

  __half *xh, *wg, *wu, *wd, *hb;
  cudaGetSymbolAddress((void**)&xh, g_xh);
  cudaGetSymbolAddress((void**)&wg, g_wg);
  cudaGetSymbolAddress((void**)&wu, g_wu);
  cudaGetSymbolAddress((void**)&wd, g_wd);
  cudaGetSymbolAddress((void**)&hb, g_hbuf);

  cudaFuncSetAttribute(fused_mlp, cudaFuncAttributeMaxDynamicSharedMemorySize, SMEM_BYTES);

  convert_xgu<<<(N4TOT3 + 255) / 256, 256>>>(x, gate_w, up_w, xh, wg, wu);

  fused_mlp<<<304, 256, SMEM_BYTES>>>(xh, wg, wu, gate_s, up_s, hb,
                                      down_w, wd, down_s, out);
}